// round 11
// baseline (speedup 1.0000x reference)
#include <cuda_runtime.h>
#include <cstdint>

#define NN 2048
#define TT 16
#define DD 16
#define HH 64
#define NP (NN*NN)          // 4194304 pairs
#define NP2 (NP/2)          // 2097152 pair-pairs (512B each)
#define NBATCH (NP2/16)     // 131072 batches (16 p2 = 32 pairs = 8KB each)
#define CHUNK 4             // batches per atomic grab
#define NCHUNK (NBATCH/CHUNK)

// ---------------- device scratch (static, no allocation) ----------------
__device__ __align__(16) float g_E0[NP];          // 16 MB: exp(leaky(rel.w1+b1)+mask)
__device__ __align__(16) float g_emb[NN*HH];      // LSTM last hidden
__device__ __align__(16) float g_era[NN];         // exp(leaky(emb.w2+b2)+leaky(emb.w3+b3))
__device__ __align__(16) float g_zpart[32*NN];    // column-sum partials (32 row-chunks)
__device__ __align__(16) float g_q[NN];           // iZ_j * (emb[j].w4b)
__device__ __align__(16) float g_base[NN];        // b4 + emb[j].w4a
__device__ unsigned int g_cnt = 0;                // rel work-steal counter

__device__ __forceinline__ float sigm(float v) {
    v = fminf(fmaxf(v, -30.f), 30.f);
    return __fdividef(1.f, 1.f + __expf(-v));
}
__device__ __forceinline__ float tanhx(float v) {
    v = fminf(fmaxf(v, -30.f), 30.f);
    float e = __expf(-2.f * v);
    return __fdividef(1.f - e, 1.f + e);
}
__device__ __forceinline__ float leaky(float v) { return fmaxf(0.2f * v, v); }

// f32x2 helpers
__device__ __forceinline__ void fma2(unsigned long long& acc,
                                     unsigned long long a, unsigned long long b) {
    asm("fma.rn.f32x2 %0, %1, %2, %0;" : "+l"(acc) : "l"(a), "l"(b));
}
__device__ __forceinline__ unsigned long long mul2(unsigned long long a,
                                                   unsigned long long b) {
    unsigned long long r;
    asm("mul.rn.f32x2 %0, %1, %2;" : "=l"(r) : "l"(a), "l"(b));
    return r;
}
__device__ __forceinline__ unsigned long long pk2(float x, float y) {
    unsigned long long r;
    asm("mov.b64 %0, {%1, %2};" : "=l"(r) : "f"(x), "f"(y));
    return r;
}
__device__ __forceinline__ void upk2(float& x, float& y, unsigned long long v) {
    asm("mov.b64 {%0, %1}, %2;" : "=f"(x), "=f"(y) : "l"(v));
}
__device__ __forceinline__ void lds2x64(unsigned long long& a, unsigned long long& b,
                                        unsigned int addr) {
    asm volatile("ld.shared.v2.b64 {%0, %1}, [%2];" : "=l"(a), "=l"(b) : "r"(addr));
}
__device__ __forceinline__ unsigned int smem_u32(const void* p) {
    unsigned int a;
    asm("{ .reg .u64 t; cvta.to.shared.u64 t, %1; cvt.u32.u64 %0, t; }" : "=r"(a) : "l"(p));
    return a;
}

// ---------------- K1: fused LSTM + work-stealing relation stream -------------
#define K1_BLOCKS 148
#define LSTM_BLOCKS 128
#define K1_THREADS 768

// smem float offsets (LSTM blocks only use these)
#define SM_WHH 0          // 64*64*4 floats (layout [(k*64+j)*4 + gate])
#define SM_WIH 16384      // 16*64*4
#define SM_X   20480      // 16 rows * 256
#define SM_H   24576      // 2 * 16 * 64
#define SM_TOT 26624      // floats -> 106496 bytes

// one batch of 16 pair-pairs (32 pairs = 8KB of rel); MLP=16
__device__ __forceinline__ void rel_batch(
    const float4* __restrict__ rel4, const float* __restrict__ mask,
    long base, int lane, unsigned long long w01, unsigned long long w23,
    float b1v)
{
    const int myk = lane & 15;
    long p = 2 * base + 2 * myk + (lane >> 4);
    float mk = __ldcs(mask + p);

    float4 v[16];
    const float4* src = rel4 + base * 32 + lane;
    #pragma unroll
    for (int k = 0; k < 16; k++) v[k] = __ldcs(src + k * 32);

    float myS = 0.f;
    #pragma unroll
    for (int k = 0; k < 16; k++) {
        unsigned long long acc = mul2(pk2(v[k].x, v[k].y), w01);
        fma2(acc, pk2(v[k].z, v[k].w), w23);
        float lo, hi;
        upk2(lo, hi, acc);
        float s = lo + hi;
        // width-16 XOR butterfly = allreduce within each 16-lane half
        s += __shfl_xor_sync(0xffffffffu, s, 8, 16);
        s += __shfl_xor_sync(0xffffffffu, s, 4, 16);
        s += __shfl_xor_sync(0xffffffffu, s, 2, 16);
        s += __shfl_xor_sync(0xffffffffu, s, 1, 16);
        if (myk == k) myS = s;    // lane keeps its own pair's sum
    }
    g_E0[p] = __expf(leaky(myS + b1v) + mk);
}

// work-steal loop with pipelined grabs: next chunk's atomic issued before
// processing the current one, so its ~300cyc latency hides under compute
__device__ __forceinline__ void rel_loop(
    const float4* __restrict__ rel4, const float* __restrict__ mask,
    int lane, unsigned long long w01, unsigned long long w23, float b1v)
{
    unsigned int c = 0;
    if (lane == 0) c = atomicAdd(&g_cnt, 1u);
    c = __shfl_sync(0xffffffffu, c, 0);
    while (c < NCHUNK) {
        unsigned int cn = 0;
        if (lane == 0) cn = atomicAdd(&g_cnt, 1u);   // issue early
        long base0 = (long)c * (CHUNK * 16);
        #pragma unroll
        for (int b = 0; b < CHUNK; b++)
            rel_batch(rel4, mask, base0 + b * 16, lane, w01, w23, b1v);
        c = __shfl_sync(0xffffffffu, cn, 0);
    }
}

__global__ __launch_bounds__(K1_THREADS, 1)
void k1_lstm_rel(const float* __restrict__ x, const float* __restrict__ rel,
                 const float* __restrict__ mask,
                 const float* __restrict__ Wih, const float* __restrict__ Whh,
                 const float* __restrict__ bih, const float* __restrict__ bhh,
                 const float* __restrict__ w1, const float* __restrict__ b1p)
{
    extern __shared__ float sm[];
    const int tid = threadIdx.x;
    const int w = tid >> 5;
    const int bx = blockIdx.x;
    const bool lstmB = (bx < LSTM_BLOCKS);
    const int lane = tid & 31;
    const int sub = lane & 15;
    const float4 w1v = *(const float4*)(w1 + sub * 4);
    const unsigned long long w01 = pk2(w1v.x, w1v.y);
    const unsigned long long w23 = pk2(w1v.z, w1v.w);
    const float b1v = __ldg(b1p);
    const float4* rel4 = (const float4*)rel;

    if (lstmB && w < 8) {
        // ---------------- LSTM role: 256 threads, 16 rows, f32x2 gates -------
        const int j  = tid & 63;
        const int rg = tid >> 6;
        const int r0 = rg * 4;
        const int row0 = bx * 16;

        float* Whh_P = sm + SM_WHH;
        float* Wih_P = sm + SM_WIH;
        float* x_s   = sm + SM_X;
        float* h_s   = sm + SM_H;

        for (int idx = tid; idx < 16384; idx += 256) {
            int gr = idx >> 6, k = idx & 63;
            int gate = gr >> 6, jj = gr & 63;
            Whh_P[((k << 6) + jj) * 4 + gate] = Whh[idx];
        }
        for (int idx = tid; idx < 4096; idx += 256) {
            int gr = idx >> 4, d = idx & 15;
            int gate = gr >> 6, jj = gr & 63;
            Wih_P[((d << 6) + jj) * 4 + gate] = Wih[idx];
        }
        for (int idx = tid; idx < 16 * TT * DD; idx += 256)
            x_s[idx] = x[(size_t)row0 * TT * DD + idx];
        for (int idx = tid; idx < 2048; idx += 256) h_s[idx] = 0.f;

        const unsigned long long bIF = pk2(bih[j] + bhh[j], bih[64 + j] + bhh[64 + j]);
        const unsigned long long bGO = pk2(bih[128 + j] + bhh[128 + j], bih[192 + j] + bhh[192 + j]);

        const unsigned int wih_a = smem_u32(Wih_P) + (unsigned)j * 16;
        const unsigned int whh_a = smem_u32(Whh_P) + (unsigned)j * 16;

        float c[4] = {0.f, 0.f, 0.f, 0.f};
        asm volatile("bar.sync 1, 256;" ::: "memory");

        int buf = 0;
        for (int t = 0; t < TT; t++) {
            unsigned long long aIF[4], aGO[4];
            #pragma unroll
            for (int q = 0; q < 4; q++) { aIF[q] = bIF; aGO[q] = bGO; }

            const float* xb = x_s + t * DD;
            #pragma unroll
            for (int d = 0; d < DD; d++) {
                unsigned long long wIF, wGO;
                lds2x64(wIF, wGO, wih_a + (unsigned)d * 1024);
                #pragma unroll
                for (int q = 0; q < 4; q++) {
                    float xv = xb[(r0 + q) * 256 + d];
                    unsigned long long x2 = pk2(xv, xv);
                    fma2(aIF[q], wIF, x2);
                    fma2(aGO[q], wGO, x2);
                }
            }
            const float* hb = h_s + buf * 1024;
            #pragma unroll 8
            for (int k = 0; k < HH; k++) {
                unsigned long long wIF, wGO;
                lds2x64(wIF, wGO, whh_a + (unsigned)k * 1024);
                #pragma unroll
                for (int q = 0; q < 4; q++) {
                    float hv = hb[(r0 + q) * 64 + k];
                    unsigned long long h2 = pk2(hv, hv);
                    fma2(aIF[q], wIF, h2);
                    fma2(aGO[q], wGO, h2);
                }
            }
            float* hn = h_s + (buf ^ 1) * 1024;
            #pragma unroll
            for (int q = 0; q < 4; q++) {
                float ai, af, ag, ao;
                upk2(ai, af, aIF[q]);
                upk2(ag, ao, aGO[q]);
                float ig = sigm(ai);
                float fg = sigm(af);
                float gg = tanhx(ag);
                float og = sigm(ao);
                c[q] = fmaf(fg, c[q], ig * gg);
                float hv = og * tanhx(c[q]);
                hn[(r0 + q) * 64 + j] = hv;
                if (t == TT - 1) g_emb[(size_t)(row0 + r0 + q) * 64 + j] = hv;
            }
            asm volatile("bar.sync 1, 256;" ::: "memory");
            buf ^= 1;
        }
        // LSTM done -> join the relation stream
        rel_loop(rel4, mask, lane, w01, w23, b1v);
    } else {
        // dedicated relation warps start immediately
        rel_loop(rel4, mask, lane, w01, w23, b1v);
    }
}

// ---------------- K2b: fused era + column-sum partials -----------------------
// grid (NN/256=8, 32): bx = j-block of 256, by = row chunk of 64
__global__ __launch_bounds__(256) void k2b_colsum(
    const float* __restrict__ w2, const float* __restrict__ b2,
    const float* __restrict__ w3, const float* __restrict__ b3)
{
    __shared__ float w2s[64], w3s[64], era_s[64];
    int tid = threadIdx.x;
    if (tid < 64) { w2s[tid] = w2[tid]; w3s[tid] = w3[tid]; }
    __syncthreads();
    int i0 = blockIdx.y * 64;
    if (tid < 64) {
        const float4* e4 = (const float4*)(g_emb + (size_t)(i0 + tid) * 64);
        float s2 = 0.f, s3 = 0.f;
        #pragma unroll
        for (int k = 0; k < 16; k++) {
            float4 e = e4[k];
            float4 a = ((const float4*)w2s)[k];
            float4 b = ((const float4*)w3s)[k];
            s2 += e.x*a.x + e.y*a.y + e.z*a.z + e.w*a.w;
            s3 += e.x*b.x + e.y*b.y + e.z*b.z + e.w*b.w;
        }
        s2 += __ldg(b2); s3 += __ldg(b3);
        float era = __expf(leaky(s2) + leaky(s3));
        era_s[tid] = era;
        if (blockIdx.x == 0) g_era[i0 + tid] = era;
    }
    __syncthreads();
    int j = blockIdx.x * 256 + tid;
    float acc = 0.f;
    #pragma unroll 8
    for (int r = 0; r < 64; r++)
        acc = fmaf(era_s[r], g_E0[(size_t)(i0 + r) * NN + j], acc);
    g_zpart[blockIdx.y * NN + j] = acc;
}

// ---------------- K3q: q[j] = iZ_j*(emb[j].w4b); base[j] = b4 + emb[j].w4a ---
__global__ __launch_bounds__(128) void k3_q(const float* __restrict__ w4,
                                            const float* __restrict__ b4)
{
    __shared__ float w4s[128];
    int tid = threadIdx.x;
    w4s[tid] = w4[tid];
    __syncthreads();
    int j = blockIdx.x * 128 + tid;
    float s = 0.f;
    #pragma unroll
    for (int c = 0; c < 32; c++) s += g_zpart[c * NN + j];
    float iZ = __fdividef(1.f, s);
    const float4* e4 = (const float4*)(g_emb + (size_t)j * 64);
    float da = 0.f, db = 0.f;
    #pragma unroll
    for (int k = 0; k < 16; k++) {
        float4 e = e4[k];
        float4 wa = ((const float4*)w4s)[k];
        float4 wb = ((const float4*)w4s)[16 + k];
        da += e.x*wa.x + e.y*wa.y + e.z*wa.z + e.w*wa.w;
        db += e.x*wb.x + e.y*wb.y + e.z*wb.z + e.w*wb.w;
    }
    g_q[j] = iZ * db;
    g_base[j] = __ldg(b4) + da;
}

// ---------------- K4f: out[i] = leaky(base_i + era_i * sum_j E0[i,j]*q_j) ----
// grid 1024 blocks x 128 threads; 2 warps per row (half-row each)
__global__ __launch_bounds__(128) void k4_final(float* __restrict__ out)
{
    __shared__ float part[4];
    int tid = threadIdx.x;
    int wid = tid >> 5, lane = tid & 31;
    if (blockIdx.x == 0 && tid == 0) g_cnt = 0;   // reset work-steal counter

    int i = blockIdx.x * 2 + (wid >> 1);          // 2 rows per block
    int half = wid & 1;                            // half-row per warp
    const float4* e0 = (const float4*)(g_E0 + (size_t)i * NN) + half * 256 + lane;
    const float4* q4 = (const float4*)g_q + half * 256 + lane;
    float acc = 0.f;
    #pragma unroll
    for (int m = 0; m < 8; m++) {
        float4 v = __ldg(e0 + m * 32);
        float4 qv = __ldg(q4 + m * 32);
        acc += v.x*qv.x + v.y*qv.y + v.z*qv.z + v.w*qv.w;
    }
    #pragma unroll
    for (int d = 16; d; d >>= 1)
        acc += __shfl_xor_sync(0xffffffffu, acc, d);
    if (lane == 0) part[wid] = acc;
    __syncthreads();
    if (tid < 2) {
        int ii = blockIdx.x * 2 + tid;
        float s = part[2 * tid] + part[2 * tid + 1];
        out[ii] = leaky(g_base[ii] + __ldg(g_era + ii) * s);
    }
}

// ---------------- launch ------------------------------------------------------
extern "C" void kernel_launch(void* const* d_in, const int* in_sizes, int n_in,
                              void* d_out, int out_size)
{
    const float* x    = (const float*)d_in[0];
    const float* rel  = (const float*)d_in[1];
    const float* mask = (const float*)d_in[2];
    const float* Wih  = (const float*)d_in[3];
    const float* Whh  = (const float*)d_in[4];
    const float* bih  = (const float*)d_in[5];
    const float* bhh  = (const float*)d_in[6];
    const float* w1   = (const float*)d_in[7];
    const float* b1   = (const float*)d_in[8];
    const float* w2   = (const float*)d_in[9];
    const float* b2   = (const float*)d_in[10];
    const float* w3   = (const float*)d_in[11];
    const float* b3   = (const float*)d_in[12];
    const float* w4   = (const float*)d_in[13];
    const float* b4   = (const float*)d_in[14];

    cudaFuncSetAttribute(k1_lstm_rel, cudaFuncAttributeMaxDynamicSharedMemorySize,
                         SM_TOT * (int)sizeof(float));

    k1_lstm_rel<<<K1_BLOCKS, K1_THREADS, SM_TOT * sizeof(float)>>>(
        x, rel, mask, Wih, Whh, bih, bhh, w1, b1);
    k2b_colsum<<<dim3(NN / 256, 32), 256>>>(w2, b2, w3, b3);
    k3_q<<<NN / 128, 128>>>(w4, b4);
    k4_final<<<NN / 2, 128>>>((float*)d_out);
}